// round 2
// baseline (speedup 1.0000x reference)
#include <cuda_runtime.h>
#include <cstdint>
#include <cstddef>

#define NN 8192
#define INF 512
#define OF 64
#define SPLITJ 8
#define JCHUNK (NN / SPLITJ)

// ---------------- device scratch (no allocations allowed) ----------------
__device__ float g_WH[NN * OF];                      // h @ W            (2 MB)
__device__ float g_wh1[NN], g_wh2[NN];
__device__ float g_e1[NN], g_f1[NN];                 // exp(wh1), exp(.01*wh1)
__device__ float g_e2[NN], g_f2[NN];                 // exp(wh2), exp(.01*wh2)
__device__ float g_num[(size_t)SPLITJ * NN * OF];    // partial numerators (16 MB)
__device__ float g_den[SPLITJ * NN];                 // partial denominators

// ---------------- f32x2 helpers (Blackwell packed fp32) ----------------
__device__ __forceinline__ unsigned long long dup2(float x) {
    unsigned int xi = __float_as_uint(x);
    unsigned long long r;
    asm("mov.b64 %0, {%1, %1};" : "=l"(r) : "r"(xi));
    return r;
}
__device__ __forceinline__ void fma2(unsigned long long& d, unsigned long long a,
                                     unsigned long long b) {
    asm("fma.rn.f32x2 %0, %1, %2, %0;" : "+l"(d) : "l"(a), "l"(b));
}
__device__ __forceinline__ float2 unpack2(unsigned long long v) {
    unsigned int lo, hi;
    asm("mov.b64 {%0, %1}, %2;" : "=r"(lo), "=r"(hi) : "l"(v));
    return make_float2(__uint_as_float(lo), __uint_as_float(hi));
}

// ---------------- kernel 1: WH = h @ W  (8192x512 @ 512x64) ----------------
__global__ void gemm_wh(const float* __restrict__ h, const float* __restrict__ Wm) {
    __shared__ float hs[64][36];   // 64 rows x 32 k (padded)
    __shared__ float Ws[32][68];   // 32 k x 64 cols (padded)
    const int tid = threadIdx.x;
    const int ibase = blockIdx.x * 64;
    const int tx = tid & 15, ty = tid >> 4;
    const int r0 = ty * 4, c0 = tx * 4;
    float acc[4][4] = {};

    for (int kt = 0; kt < INF; kt += 32) {
        __syncthreads();
#pragma unroll
        for (int q = 0; q < 2; q++) {
            int idx = tid + q * 256;            // 0..511 float4 slots
            int row = idx >> 3, kq = idx & 7;   // h tile: 64 rows x 8 float4
            float4 hv = *(const float4*)&h[(size_t)(ibase + row) * INF + kt + kq * 4];
            *(float4*)&hs[row][kq * 4] = hv;
            int krow = idx >> 4, cq = idx & 15; // W tile: 32 k x 16 float4
            float4 wv = *(const float4*)&Wm[(size_t)(kt + krow) * OF + cq * 4];
            *(float4*)&Ws[krow][cq * 4] = wv;
        }
        __syncthreads();
#pragma unroll
        for (int k = 0; k < 32; k++) {
            float4 b = *(const float4*)&Ws[k][c0];
#pragma unroll
            for (int r = 0; r < 4; r++) {
                float av = hs[r0 + r][k];
                acc[r][0] += av * b.x;
                acc[r][1] += av * b.y;
                acc[r][2] += av * b.z;
                acc[r][3] += av * b.w;
            }
        }
    }
#pragma unroll
    for (int r = 0; r < 4; r++) {
        float4 o = make_float4(acc[r][0], acc[r][1], acc[r][2], acc[r][3]);
        *(float4*)&g_WH[(size_t)(ibase + r0 + r) * OF + c0] = o;
    }
}

// ---------------- kernel 2: per-row stats: wh1, wh2 and factored exps ----------------
__global__ void row_stats(const float* __restrict__ a) {
    const int lane = threadIdx.x & 31;
    const int wid = threadIdx.x >> 5;
    const int row = blockIdx.x * 8 + wid;
    float v0 = g_WH[row * OF + lane];
    float v1 = g_WH[row * OF + 32 + lane];
    float p1 = v0 * a[lane] + v1 * a[lane + 32];
    float p2 = v0 * a[64 + lane] + v1 * a[96 + lane];
#pragma unroll
    for (int off = 16; off; off >>= 1) {
        p1 += __shfl_xor_sync(0xffffffffu, p1, off);
        p2 += __shfl_xor_sync(0xffffffffu, p2, off);
    }
    if (lane == 0) {
        g_wh1[row] = p1;
        g_wh2[row] = p2;
        g_e1[row] = expf(p1);
        g_f1[row] = expf(0.01f * p1);
        g_e2[row] = expf(p2);
        g_f2[row] = expf(0.01f * p2);
    }
}

// ---------------- kernel 3: fused masked-softmax-weight GEMM (partials) ----------------
// Block: 128 threads. Output tile: 128 rows x 64 features. j split SPLITJ ways.
// P_ij = adj_ij * ( s>0 ? e1_i*e2_j : f1_i*f2_j ),  s = wh1_i + wh2_j
// num[i,:] += P_ij * WH[j,:]   den[i] += P_ij
__global__ void __launch_bounds__(128, 4) attn(const int* __restrict__ adj) {
    __shared__ float ws[128][37];   // weights tile, stride 37: conflict-free everywhere
    __shared__ float whs[32][68];   // WH tile [j][f], padded
    __shared__ float rw1[128], re1[128], rf1[128];

    const int tid = threadIdx.x;
    const int lane = tid & 31;
    const int warp = tid >> 5;
    const int itile = blockIdx.x;
    const int split = blockIdx.y;
    const int ibase = itile * 128;

    // row params for this block's 128 rows
    {
        int gi = ibase + tid;
        rw1[tid] = g_wh1[gi];
        re1[tid] = g_e1[gi];
        rf1[tid] = g_f1[gi];
    }

    // phase-3 thread tile: 8 rows x 8 features
    const int fg = tid & 7;       // feature group: f0 = fg*8
    const int igq = tid >> 3;     // row group:     i0 = igq*8
    const int i0 = igq * 8;

    unsigned long long acc[8][4];
#pragma unroll
    for (int r = 0; r < 8; r++)
#pragma unroll
        for (int c = 0; c < 4; c++) acc[r][c] = 0ull;

    float dsum = 0.f;  // denominator for local row `tid`

    const int jbase = split * JCHUNK;
    for (int jt = jbase; jt < jbase + JCHUNK; jt += 32) {
        // prefetch WH tile into regs (LDG in flight across the sync)
        float4 wv[4];
#pragma unroll
        for (int q = 0; q < 4; q++) {
            int idx = tid + q * 128;            // 0..511 float4 slots
            int jr = idx >> 4, fq = idx & 15;
            wv[q] = *(const float4*)&g_WH[(size_t)(jt + jr) * OF + fq * 4];
        }
        // per-j params for my lane's j
        const int j = jt + lane;
        const float w2j = g_wh2[j];
        const float e2j = g_e2[j];
        const float f2j = g_f2[j];

        __syncthreads();  // previous iteration done reading ws/whs
#pragma unroll
        for (int q = 0; q < 4; q++) {
            int idx = tid + q * 128;
            int jr = idx >> 4, fq = idx & 15;
            *(float4*)&whs[jr][fq * 4] = wv[q];
        }
        // phase 1: weight generation. warp w owns local rows [32w, 32w+32)
        const int* arow = adj + (size_t)(ibase + warp * 32) * NN + j;
#pragma unroll 8
        for (int r = 0; r < 32; r++) {
            int il = warp * 32 + r;
            int av = arow[r * NN];
            float s = rw1[il] + w2j;
            float w = (s > 0.f) ? re1[il] * e2j : rf1[il] * f2j;
            w = av ? w : 0.f;
            ws[il][lane] = w;
        }
        __syncthreads();

        // phase 1.5: denominator partial, thread tid <-> local row tid
        {
            float s0 = 0.f, s1 = 0.f, s2 = 0.f, s3 = 0.f;
#pragma unroll
            for (int jj = 0; jj < 32; jj += 4) {
                s0 += ws[tid][jj];
                s1 += ws[tid][jj + 1];
                s2 += ws[tid][jj + 2];
                s3 += ws[tid][jj + 3];
            }
            dsum += (s0 + s1) + (s2 + s3);
        }

        // phase 3: packed-f32x2 rank-32 update, 8 rows x 8 features per thread
#pragma unroll 4
        for (int jj = 0; jj < 32; jj++) {
            const float* wr = &whs[jj][fg * 8];
            unsigned long long p0 = *(const unsigned long long*)(wr + 0);
            unsigned long long p1 = *(const unsigned long long*)(wr + 2);
            unsigned long long p2 = *(const unsigned long long*)(wr + 4);
            unsigned long long p3 = *(const unsigned long long*)(wr + 6);
#pragma unroll
            for (int r = 0; r < 8; r++) {
                unsigned long long wvv = dup2(ws[i0 + r][jj]);
                fma2(acc[r][0], wvv, p0);
                fma2(acc[r][1], wvv, p1);
                fma2(acc[r][2], wvv, p2);
                fma2(acc[r][3], wvv, p3);
            }
        }
    }

    // write partials
#pragma unroll
    for (int r = 0; r < 8; r++) {
        float2 a0 = unpack2(acc[r][0]);
        float2 a1 = unpack2(acc[r][1]);
        float2 a2 = unpack2(acc[r][2]);
        float2 a3 = unpack2(acc[r][3]);
        size_t off = ((size_t)split * NN + (size_t)(ibase + i0 + r)) * OF + fg * 8;
        *(float4*)&g_num[off] = make_float4(a0.x, a0.y, a1.x, a1.y);
        *(float4*)&g_num[off + 4] = make_float4(a2.x, a2.y, a3.x, a3.y);
    }
    g_den[split * NN + ibase + tid] = dsum;
}

// ---------------- kernel 4: reduce partials, divide, ELU ----------------
__global__ void finalize_k(float* __restrict__ out) {
    int idx = blockIdx.x * 256 + threadIdx.x;   // 0 .. NN*OF-1
    int i = idx >> 6;
    int f = idx & 63;
    float num = 0.f, den = 0.f;
#pragma unroll
    for (int s = 0; s < SPLITJ; s++) {
        num += g_num[((size_t)s * NN + i) * OF + f];
        den += g_den[s * NN + i];
    }
    float x = num / den;
    out[idx] = (x > 0.f) ? x : expm1f(x);
}

// ---------------- launch ----------------
extern "C" void kernel_launch(void* const* d_in, const int* in_sizes, int n_in,
                              void* d_out, int out_size) {
    const float* h = nullptr;
    const int* adj = nullptr;
    const float* Wm = nullptr;
    const float* a = nullptr;
    for (int i = 0; i < n_in; i++) {
        switch (in_sizes[i]) {
            case NN * INF:  h   = (const float*)d_in[i]; break;   // 4,194,304
            case NN * NN:   adj = (const int*)d_in[i];   break;   // 67,108,864 (wraps? no: fits int)
            case INF * OF:  Wm  = (const float*)d_in[i]; break;   // 32,768
            case 2 * OF:    a   = (const float*)d_in[i]; break;   // 128
            default: break;
        }
    }

    gemm_wh<<<NN / 64, 256>>>(h, Wm);
    row_stats<<<NN / 8, 256>>>(a);
    dim3 g(NN / 128, SPLITJ);
    attn<<<g, 128>>>(adj);
    finalize_k<<<(NN * OF) / 256, 256>>>((float*)d_out);
}

// round 3
// speedup vs baseline: 1.0114x; 1.0114x over previous
#include <cuda_runtime.h>
#include <cstdint>
#include <cstddef>

#define NN 8192
#define INF 512
#define OF 64
#define SPLITJ 8
#define JCHUNK (NN / SPLITJ)

// ---------------- device scratch (no allocations allowed) ----------------
__device__ float g_WH[NN * OF];                      // h @ W            (2 MB)
__device__ float g_wh1[NN], g_wh2[NN];
__device__ float g_e1[NN], g_f1[NN];                 // exp(wh1), exp(.01*wh1)
__device__ float g_e2[NN], g_f2[NN];                 // exp(wh2), exp(.01*wh2)
__device__ float g_num[(size_t)SPLITJ * NN * OF];    // partial numerators (16 MB)
__device__ float g_den[SPLITJ * NN];                 // partial denominators

// ---------------- f32x2 helpers (Blackwell packed fp32) ----------------
__device__ __forceinline__ unsigned long long dup2(float x) {
    unsigned int xi = __float_as_uint(x);
    unsigned long long r;
    asm("mov.b64 %0, {%1, %1};" : "=l"(r) : "r"(xi));
    return r;
}
__device__ __forceinline__ void fma2(unsigned long long& d, unsigned long long a,
                                     unsigned long long b) {
    asm("fma.rn.f32x2 %0, %1, %2, %0;" : "+l"(d) : "l"(a), "l"(b));
}
__device__ __forceinline__ float2 unpack2(unsigned long long v) {
    unsigned int lo, hi;
    asm("mov.b64 {%0, %1}, %2;" : "=r"(lo), "=r"(hi) : "l"(v));
    return make_float2(__uint_as_float(lo), __uint_as_float(hi));
}

// ---------------- kernel 1: WH = h @ W  (8192x512 @ 512x64) ----------------
__global__ void gemm_wh(const float* __restrict__ h, const float* __restrict__ Wm) {
    __shared__ float hs[64][36];   // 64 rows x 32 k (padded)
    __shared__ float Ws[32][68];   // 32 k x 64 cols (padded)
    const int tid = threadIdx.x;
    const int ibase = blockIdx.x * 64;
    const int tx = tid & 15, ty = tid >> 4;
    const int r0 = ty * 4, c0 = tx * 4;
    float acc[4][4] = {};

    for (int kt = 0; kt < INF; kt += 32) {
        __syncthreads();
#pragma unroll
        for (int q = 0; q < 2; q++) {
            int idx = tid + q * 256;            // 0..511 float4 slots
            int row = idx >> 3, kq = idx & 7;   // h tile: 64 rows x 8 float4
            float4 hv = *(const float4*)&h[(size_t)(ibase + row) * INF + kt + kq * 4];
            *(float4*)&hs[row][kq * 4] = hv;
            int krow = idx >> 4, cq = idx & 15; // W tile: 32 k x 16 float4
            float4 wv = *(const float4*)&Wm[(size_t)(kt + krow) * OF + cq * 4];
            *(float4*)&Ws[krow][cq * 4] = wv;
        }
        __syncthreads();
#pragma unroll
        for (int k = 0; k < 32; k++) {
            float4 b = *(const float4*)&Ws[k][c0];
#pragma unroll
            for (int r = 0; r < 4; r++) {
                float av = hs[r0 + r][k];
                acc[r][0] += av * b.x;
                acc[r][1] += av * b.y;
                acc[r][2] += av * b.z;
                acc[r][3] += av * b.w;
            }
        }
    }
#pragma unroll
    for (int r = 0; r < 4; r++) {
        float4 o = make_float4(acc[r][0], acc[r][1], acc[r][2], acc[r][3]);
        *(float4*)&g_WH[(size_t)(ibase + r0 + r) * OF + c0] = o;
    }
}

// ---------------- kernel 2: per-row stats: wh1, wh2 and factored exps ----------------
__global__ void row_stats(const float* __restrict__ a) {
    const int lane = threadIdx.x & 31;
    const int wid = threadIdx.x >> 5;
    const int row = blockIdx.x * 8 + wid;
    float v0 = g_WH[row * OF + lane];
    float v1 = g_WH[row * OF + 32 + lane];
    float p1 = v0 * a[lane] + v1 * a[lane + 32];
    float p2 = v0 * a[64 + lane] + v1 * a[96 + lane];
#pragma unroll
    for (int off = 16; off; off >>= 1) {
        p1 += __shfl_xor_sync(0xffffffffu, p1, off);
        p2 += __shfl_xor_sync(0xffffffffu, p2, off);
    }
    if (lane == 0) {
        g_wh1[row] = p1;
        g_wh2[row] = p2;
        g_e1[row] = expf(p1);
        g_f1[row] = expf(0.01f * p1);
        g_e2[row] = expf(p2);
        g_f2[row] = expf(0.01f * p2);
    }
}

// ---------------- kernel 3: fused masked-softmax-weight GEMM (partials) ----------------
// Block: 128 threads. Output tile: 128 rows x 64 features. j split SPLITJ ways.
// P_ij = adj_ij * ( s>0 ? e1_i*e2_j : f1_i*f2_j ),  s = wh1_i + wh2_j
// num[i,:] += P_ij * WH[j,:]   den[i] += P_ij
__global__ void __launch_bounds__(128, 4) attn(const int* __restrict__ adj) {
    __shared__ float ws[128][37];   // weights tile, stride 37: conflict-free everywhere
    __shared__ float whs[32][68];   // WH tile [j][f], padded
    __shared__ float rw1[128], re1[128], rf1[128];

    const int tid = threadIdx.x;
    const int lane = tid & 31;
    const int warp = tid >> 5;
    const int itile = blockIdx.x;
    const int split = blockIdx.y;
    const int ibase = itile * 128;

    // row params for this block's 128 rows
    {
        int gi = ibase + tid;
        rw1[tid] = g_wh1[gi];
        re1[tid] = g_e1[gi];
        rf1[tid] = g_f1[gi];
    }

    // phase-3 thread tile: 8 rows x 8 features
    const int fg = tid & 7;       // feature group: f0 = fg*8
    const int igq = tid >> 3;     // row group:     i0 = igq*8
    const int i0 = igq * 8;

    unsigned long long acc[8][4];
#pragma unroll
    for (int r = 0; r < 8; r++)
#pragma unroll
        for (int c = 0; c < 4; c++) acc[r][c] = 0ull;

    float dsum = 0.f;  // denominator for local row `tid`

    const int jbase = split * JCHUNK;
    for (int jt = jbase; jt < jbase + JCHUNK; jt += 32) {
        // prefetch WH tile into regs (LDG in flight across the sync)
        float4 wv[4];
#pragma unroll
        for (int q = 0; q < 4; q++) {
            int idx = tid + q * 128;            // 0..511 float4 slots
            int jr = idx >> 4, fq = idx & 15;
            wv[q] = *(const float4*)&g_WH[(size_t)(jt + jr) * OF + fq * 4];
        }
        // per-j params for my lane's j
        const int j = jt + lane;
        const float w2j = g_wh2[j];
        const float e2j = g_e2[j];
        const float f2j = g_f2[j];

        __syncthreads();  // previous iteration done reading ws/whs
#pragma unroll
        for (int q = 0; q < 4; q++) {
            int idx = tid + q * 128;
            int jr = idx >> 4, fq = idx & 15;
            *(float4*)&whs[jr][fq * 4] = wv[q];
        }
        // phase 1: weight generation. warp w owns local rows [32w, 32w+32)
        const int* arow = adj + (size_t)(ibase + warp * 32) * NN + j;
#pragma unroll 8
        for (int r = 0; r < 32; r++) {
            int il = warp * 32 + r;
            int av = arow[r * NN];
            float s = rw1[il] + w2j;
            float w = (s > 0.f) ? re1[il] * e2j : rf1[il] * f2j;
            w = av ? w : 0.f;
            ws[il][lane] = w;
        }
        __syncthreads();

        // phase 1.5: denominator partial, thread tid <-> local row tid
        {
            float s0 = 0.f, s1 = 0.f, s2 = 0.f, s3 = 0.f;
#pragma unroll
            for (int jj = 0; jj < 32; jj += 4) {
                s0 += ws[tid][jj];
                s1 += ws[tid][jj + 1];
                s2 += ws[tid][jj + 2];
                s3 += ws[tid][jj + 3];
            }
            dsum += (s0 + s1) + (s2 + s3);
        }

        // phase 3: packed-f32x2 rank-32 update, 8 rows x 8 features per thread
#pragma unroll 4
        for (int jj = 0; jj < 32; jj++) {
            const float* wr = &whs[jj][fg * 8];
            unsigned long long p0 = *(const unsigned long long*)(wr + 0);
            unsigned long long p1 = *(const unsigned long long*)(wr + 2);
            unsigned long long p2 = *(const unsigned long long*)(wr + 4);
            unsigned long long p3 = *(const unsigned long long*)(wr + 6);
#pragma unroll
            for (int r = 0; r < 8; r++) {
                unsigned long long wvv = dup2(ws[i0 + r][jj]);
                fma2(acc[r][0], wvv, p0);
                fma2(acc[r][1], wvv, p1);
                fma2(acc[r][2], wvv, p2);
                fma2(acc[r][3], wvv, p3);
            }
        }
    }

    // write partials
#pragma unroll
    for (int r = 0; r < 8; r++) {
        float2 a0 = unpack2(acc[r][0]);
        float2 a1 = unpack2(acc[r][1]);
        float2 a2 = unpack2(acc[r][2]);
        float2 a3 = unpack2(acc[r][3]);
        size_t off = ((size_t)split * NN + (size_t)(ibase + i0 + r)) * OF + fg * 8;
        *(float4*)&g_num[off] = make_float4(a0.x, a0.y, a1.x, a1.y);
        *(float4*)&g_num[off + 4] = make_float4(a2.x, a2.y, a3.x, a3.y);
    }
    g_den[split * NN + ibase + tid] = dsum;
}

// ---------------- kernel 4: reduce partials, divide, ELU ----------------
__global__ void finalize_k(float* __restrict__ out) {
    int idx = blockIdx.x * 256 + threadIdx.x;   // 0 .. NN*OF-1
    int i = idx >> 6;
    int f = idx & 63;
    float num = 0.f, den = 0.f;
#pragma unroll
    for (int s = 0; s < SPLITJ; s++) {
        num += g_num[((size_t)s * NN + i) * OF + f];
        den += g_den[s * NN + i];
    }
    float x = num / den;
    out[idx] = (x > 0.f) ? x : expm1f(x);
}

// ---------------- launch ----------------
extern "C" void kernel_launch(void* const* d_in, const int* in_sizes, int n_in,
                              void* d_out, int out_size) {
    const float* h = nullptr;
    const int* adj = nullptr;
    const float* Wm = nullptr;
    const float* a = nullptr;
    for (int i = 0; i < n_in; i++) {
        switch (in_sizes[i]) {
            case NN * INF:  h   = (const float*)d_in[i]; break;   // 4,194,304
            case NN * NN:   adj = (const int*)d_in[i];   break;   // 67,108,864 (wraps? no: fits int)
            case INF * OF:  Wm  = (const float*)d_in[i]; break;   // 32,768
            case 2 * OF:    a   = (const float*)d_in[i]; break;   // 128
            default: break;
        }
    }

    gemm_wh<<<NN / 64, 256>>>(h, Wm);
    row_stats<<<NN / 8, 256>>>(a);
    dim3 g(NN / 128, SPLITJ);
    attn<<<g, 128>>>(adj);
    finalize_k<<<(NN * OF) / 256, 256>>>((float*)d_out);
}

// round 6
// speedup vs baseline: 1.4901x; 1.4733x over previous
#include <cuda_runtime.h>
#include <cuda_bf16.h>
#include <cstdint>
#include <cstddef>

#define NN 8192
#define INF 512
#define OF 64
#define SPLITJ 8
#define JCHUNK (NN / SPLITJ)

// ---------------- device scratch (no allocations allowed) ----------------
__device__ float g_WH[NN * OF];
__device__ float g_wh1[NN], g_wh2[NN];
__device__ float g_e1[NN], g_f1[NN], g_e2[NN], g_f2[NN];
__device__ uint4 g_Bf[(NN / 32) * 16 * 32];          // B fragments, 2MB
__device__ float g_num[(size_t)SPLITJ * NN * OF];    // 16MB partial numerators
__device__ float g_den[SPLITJ * NN];

// ---------------- helpers ----------------
// pack two f32 -> bf16x2; FIRST arg lands in the LOW half
__device__ __forceinline__ uint32_t pkbf(float lo, float hi) {
    uint32_t r;
    asm("cvt.rn.bf16x2.f32 %0, %1, %2;" : "=r"(r) : "f"(hi), "f"(lo));
    return r;
}
// hi/lo split of a pair: h = bf16x2(v), l = bf16x2(v - upcast(h))
__device__ __forceinline__ void split2(float x, float y, uint32_t& h, uint32_t& l) {
    h = pkbf(x, y);
    float lx = x - __uint_as_float(h << 16);
    float ly = y - __uint_as_float(h & 0xffff0000u);
    l = pkbf(lx, ly);
}
__device__ __forceinline__ void mma_bf16(float* c, uint32_t a0, uint32_t a1,
                                         uint32_t a2, uint32_t a3,
                                         uint32_t b0, uint32_t b1) {
    asm volatile(
        "mma.sync.aligned.m16n8k16.row.col.f32.bf16.bf16.f32 "
        "{%0,%1,%2,%3}, {%4,%5,%6,%7}, {%8,%9}, {%0,%1,%2,%3};"
        : "+f"(c[0]), "+f"(c[1]), "+f"(c[2]), "+f"(c[3])
        : "r"(a0), "r"(a1), "r"(a2), "r"(a3), "r"(b0), "r"(b1));
}

// ---------------- kernel 1: WH = h @ W (fp32 exact) ----------------
__global__ void gemm_wh(const float* __restrict__ h, const float* __restrict__ Wm) {
    __shared__ float hs[64][36];
    __shared__ float Ws[32][68];
    const int tid = threadIdx.x;
    const int ibase = blockIdx.x * 64;
    const int tx = tid & 15, ty = tid >> 4;
    const int r0 = ty * 4, c0 = tx * 4;
    float acc[4][4] = {};
    for (int kt = 0; kt < INF; kt += 32) {
        __syncthreads();
#pragma unroll
        for (int q = 0; q < 2; q++) {
            int idx = tid + q * 256;
            int row = idx >> 3, kq = idx & 7;
            *(float4*)&hs[row][kq * 4] = *(const float4*)&h[(size_t)(ibase + row) * INF + kt + kq * 4];
            int kr = idx >> 4, cq = idx & 15;
            *(float4*)&Ws[kr][cq * 4] = *(const float4*)&Wm[(size_t)(kt + kr) * OF + cq * 4];
        }
        __syncthreads();
#pragma unroll
        for (int k = 0; k < 32; k++) {
            float4 b = *(const float4*)&Ws[k][c0];
#pragma unroll
            for (int r = 0; r < 4; r++) {
                float av = hs[r0 + r][k];
                acc[r][0] += av * b.x; acc[r][1] += av * b.y;
                acc[r][2] += av * b.z; acc[r][3] += av * b.w;
            }
        }
    }
#pragma unroll
    for (int r = 0; r < 4; r++)
        *(float4*)&g_WH[(size_t)(ibase + r0 + r) * OF + c0] =
            make_float4(acc[r][0], acc[r][1], acc[r][2], acc[r][3]);
}

// ---------------- kernel 2: per-row stats (factored exp trick) ----------------
__global__ void row_stats(const float* __restrict__ a) {
    const int lane = threadIdx.x & 31;
    const int wid = threadIdx.x >> 5;
    const int row = blockIdx.x * 8 + wid;
    float v0 = g_WH[row * OF + lane];
    float v1 = g_WH[row * OF + 32 + lane];
    float p1 = v0 * a[lane] + v1 * a[lane + 32];
    float p2 = v0 * a[64 + lane] + v1 * a[96 + lane];
#pragma unroll
    for (int off = 16; off; off >>= 1) {
        p1 += __shfl_xor_sync(0xffffffffu, p1, off);
        p2 += __shfl_xor_sync(0xffffffffu, p2, off);
    }
    if (lane == 0) {
        g_wh1[row] = p1; g_wh2[row] = p2;
        g_e1[row] = expf(p1); g_f1[row] = expf(0.01f * p1);
        g_e2[row] = expf(p2); g_f2[row] = expf(0.01f * p2);
    }
}

// ---------------- kernel 2b: B (=WH) -> mma fragments, bf16 hi/lo ----------------
// frag layout per (chunk c of 32 j, k-step s, n-tile n, lane):
//   b0 low = WH[j0 + 2*(lane&3)    ][n*8 + lane>>2]   (j0 = c*32 + s*16)
//   b0 hi  = WH[j0 + 2*(lane&3) + 1][...], b1: +8 on j
__global__ void wht_prep() {
    int t = blockIdx.x * 256 + threadIdx.x;        // 0 .. 131071
    int lane = t & 31;
    int n = (t >> 5) & 7;
    int s = (t >> 8) & 1;
    int c = t >> 9;
    int j0 = c * 32 + s * 16 + 2 * (lane & 3);
    int f = n * 8 + (lane >> 2);
    float v00 = g_WH[(size_t)j0 * OF + f];
    float v01 = g_WH[(size_t)(j0 + 1) * OF + f];
    float v10 = g_WH[(size_t)(j0 + 8) * OF + f];
    float v11 = g_WH[(size_t)(j0 + 9) * OF + f];
    uint32_t bh0, bl0, bh1, bl1;
    split2(v00, v01, bh0, bl0);
    split2(v10, v11, bh1, bl1);
    g_Bf[t] = make_uint4(bh0, bh1, bl0, bl1);
}

// ---------------- kernel 3: fused masked-softmax attention GEMM (HMMA) ----------------
__global__ void __launch_bounds__(128, 4) attn(const int* __restrict__ adj) {
    __shared__ float ws[128][36];                  // warp-private 32-row slabs
    __shared__ float s_rw1[128], s_re1[128], s_rf1[128];

    const int tid = threadIdx.x;
    const int lane = tid & 31;
    const int warp = tid >> 5;
    const int ibase = blockIdx.x * 128;
    const int split = blockIdx.y;
    {
        int gi = ibase + tid;
        s_rw1[tid] = g_wh1[gi]; s_re1[tid] = g_e1[gi]; s_rf1[tid] = g_f1[gi];
    }
    __syncthreads();

    const int g = lane >> 2;
    const int qp = lane & 3;
    float acc[2][8][4];
#pragma unroll
    for (int m = 0; m < 2; m++)
#pragma unroll
        for (int n = 0; n < 8; n++)
#pragma unroll
            for (int q = 0; q < 4; q++) acc[m][n][q] = 0.f;
    float dsum = 0.f;

    const int jbase = split * JCHUNK;
    for (int jt = jbase; jt < jbase + JCHUNK; jt += 32) {
        // ---- weight generation (warp-private rows [32*warp, 32*warp+32)) ----
        const int j = jt + lane;
        const float w2j = g_wh2[j];
        const float e2j = g_e2[j];
        const float f2j = g_f2[j];
        const int* ap = adj + (size_t)(ibase + warp * 32) * NN + j;
#pragma unroll 8
        for (int r = 0; r < 32; r++) {
            int av = __ldcs(ap + (size_t)r * NN);
            int il = warp * 32 + r;
            float sv = s_rw1[il] + w2j;
            float w = (sv > 0.f) ? s_re1[il] * e2j : s_rf1[il] * f2j;
            w = av ? w : 0.f;
            ws[il][lane] = w;
            // exact fp32 row sum -> lane r keeps it
            float ts = w;
            ts += __shfl_xor_sync(0xffffffffu, ts, 16);
            ts += __shfl_xor_sync(0xffffffffu, ts, 8);
            ts += __shfl_xor_sync(0xffffffffu, ts, 4);
            ts += __shfl_xor_sync(0xffffffffu, ts, 2);
            ts += __shfl_xor_sync(0xffffffffu, ts, 1);
            if (lane == r) dsum += ts;
        }
        __syncwarp();

        // ---- 3-pass hi/lo bf16 MMA:  acc += AhBh + AlBh + AhBl ----
        const uint4* bp = g_Bf + ((size_t)(jt >> 5) * 16) * 32 + lane;
#pragma unroll
        for (int s = 0; s < 2; s++) {
            uint32_t Ah[2][4], Al[2][4];
            const int k0 = s * 16 + qp * 2;
#pragma unroll
            for (int m = 0; m < 2; m++) {
                const int ra = warp * 32 + m * 16 + g;
                float2 p0 = *(const float2*)&ws[ra][k0];
                float2 p1 = *(const float2*)&ws[ra + 8][k0];
                float2 p2 = *(const float2*)&ws[ra][k0 + 8];
                float2 p3 = *(const float2*)&ws[ra + 8][k0 + 8];
                split2(p0.x, p0.y, Ah[m][0], Al[m][0]);
                split2(p1.x, p1.y, Ah[m][1], Al[m][1]);
                split2(p2.x, p2.y, Ah[m][2], Al[m][2]);
                split2(p3.x, p3.y, Ah[m][3], Al[m][3]);
            }
#pragma unroll
            for (int n = 0; n < 8; n++) {
                uint4 B = bp[(s * 8 + n) * 32];
#pragma unroll
                for (int m = 0; m < 2; m++) {
                    mma_bf16(acc[m][n], Ah[m][0], Ah[m][1], Ah[m][2], Ah[m][3], B.x, B.y);
                    mma_bf16(acc[m][n], Al[m][0], Al[m][1], Al[m][2], Al[m][3], B.x, B.y);
                    mma_bf16(acc[m][n], Ah[m][0], Ah[m][1], Ah[m][2], Ah[m][3], B.z, B.w);
                }
            }
        }
        __syncwarp();   // ws reuse next iteration (warp-private)
    }

    g_den[split * NN + ibase + tid] = dsum;

    // ---- epilogue: write fragment accumulators ----
#pragma unroll
    for (int m = 0; m < 2; m++) {
#pragma unroll
        for (int n = 0; n < 8; n++) {
            int row = ibase + warp * 32 + m * 16 + g;
            int f = n * 8 + qp * 2;
            size_t base = ((size_t)split * NN + row) * OF + f;
            *(float2*)&g_num[base] = make_float2(acc[m][n][0], acc[m][n][1]);
            *(float2*)&g_num[base + 8 * OF] = make_float2(acc[m][n][2], acc[m][n][3]);
        }
    }
}

// ---------------- kernel 4: reduce partials, divide, ELU ----------------
__global__ void finalize_k(float* __restrict__ out) {
    int idx = blockIdx.x * 256 + threadIdx.x;
    int i = idx >> 6, f = idx & 63;
    float num = 0.f, den = 0.f;
#pragma unroll
    for (int s = 0; s < SPLITJ; s++) {
        num += g_num[((size_t)s * NN + i) * OF + f];
        den += g_den[s * NN + i];
    }
    float x = num / den;
    out[idx] = (x > 0.f) ? x : expm1f(x);
}

// ---------------- launch ----------------
extern "C" void kernel_launch(void* const* d_in, const int* in_sizes, int n_in,
                              void* d_out, int out_size) {
    const float* h = nullptr; const int* adj = nullptr;
    const float* Wm = nullptr; const float* a = nullptr;
    for (int i = 0; i < n_in; i++) {
        switch (in_sizes[i]) {
            case NN * INF: h = (const float*)d_in[i]; break;
            case NN * NN:  adj = (const int*)d_in[i]; break;
            case INF * OF: Wm = (const float*)d_in[i]; break;
            case 2 * OF:   a = (const float*)d_in[i]; break;
            default: break;
        }
    }
    gemm_wh<<<NN / 64, 256>>>(h, Wm);
    row_stats<<<NN / 8, 256>>>(a);
    wht_prep<<<512, 256>>>();
    dim3 g(NN / 128, SPLITJ);
    attn<<<g, 128>>>(adj);
    finalize_k<<<(NN * OF) / 256, 256>>>((float*)d_out);
}